// round 16
// baseline (speedup 1.0000x reference)
#include <cuda_runtime.h>
#include <cuda_bf16.h>
#include <cstdint>

// Problem constants (fixed by the dataset)
#define NC  65536   // candidates
#define BSZ 1024    // batch
#define NT  (NC+BSZ) // merged encoder rows (66560 = 520*128)
#define FD  64      // input features
#define DD  512     // model dim
#define DBD 1024    // hidden dim
#define CC  96      // context size

typedef __nv_bfloat16 bf16;

// ---------------- device scratch (allocation-free rule: __device__ globals) ----
__device__ float g_h    [(long)NT*DD];     // encoder residual out (fp32)
__device__ float g_cproj[(long)NT*DBD];    // compact: [queries | used candidates]
__device__ float g_cnorm[NT];
__device__ unsigned short g_keys[(long)BSZ*NC];  // bf16 ranking keys
__device__ unsigned g_bufA[(long)BSZ*NC];        // top-k compaction
__device__ int   g_idx  [BSZ*CC];
__device__ float g_probs[BSZ*CC];
__device__ float g_ybar [BSZ];
__device__ float g_x2   [BSZ*DD];
__device__ float g_x3   [BSZ*DD];

// used-candidate compaction
__device__ int g_flags[NC];
__device__ int g_remap[NC];
__device__ int g_list [NT];
__device__ int g_cnt  [1];

// split bf16 activation buffers (hi/lo), merged cand+query rows
__device__ bf16 g_candh[(long)NT*FD],  g_candl[(long)NT*FD];
__device__ bf16 g_hh   [(long)NT*DD],  g_hl   [(long)NT*DD];
__device__ bf16 g_th   [(long)NT*DBD], g_tl   [(long)NT*DBD];
__device__ bf16 g_hnh  [(long)NT*DD],  g_hnl  [(long)NT*DD];
__device__ bf16 g_kh   [(long)NT*DD],  g_kl   [(long)NT*DD];
__device__ bf16 g_xnh  [BSZ*DD],  g_xnl  [BSZ*DD];
__device__ bf16 g_sh   [BSZ*DBD], g_sl   [BSZ*DBD];

// split + transposed weights [N,K]
__device__ bf16 g_wlinh[DD*FD],   g_wlinl[DD*FD];
__device__ bf16 g_we1h [DBD*DD],  g_we1l [DBD*DD];
__device__ bf16 g_we2h [DD*DBD],  g_we2l [DD*DBD];
__device__ bf16 g_wKh  [DD*DD],   g_wKl  [DD*DD];
__device__ bf16 g_wT1h [DBD*DD],  g_wT1l [DBD*DD];
__device__ bf16 g_wT2h [DD*DBD],  g_wT2l [DD*DBD];
__device__ bf16 g_wp1h [DBD*DD],  g_wp1l [DBD*DD];
__device__ bf16 g_wp2h [DD*DBD],  g_wp2l [DD*DBD];

// ---------------- helpers -------------------------------------------------------
__device__ __forceinline__ void split1(float x, bf16 &h, bf16 &l) {
    h = __float2bfloat16_rn(x);
    l = __float2bfloat16_rn(x - __bfloat162float(h));
}

__device__ __forceinline__ void mma_bf16(float c[4], const unsigned a[4], const unsigned b[2]) {
    asm volatile(
        "mma.sync.aligned.m16n8k16.row.col.f32.bf16.bf16.f32 "
        "{%0,%1,%2,%3}, {%4,%5,%6,%7}, {%8,%9}, {%0,%1,%2,%3};"
        : "+f"(c[0]), "+f"(c[1]), "+f"(c[2]), "+f"(c[3])
        : "r"(a[0]), "r"(a[1]), "r"(a[2]), "r"(a[3]), "r"(b[0]), "r"(b[1]));
}

__device__ __forceinline__ void cp16s(unsigned saddr, const void* gsrc) {
    asm volatile("cp.async.cg.shared.global [%0], [%1], 16;\n" :: "r"(saddr), "l"(gsrc));
}

__device__ __forceinline__ void ldsm4(unsigned &r0, unsigned &r1, unsigned &r2,
                                      unsigned &r3, unsigned addr) {
    asm volatile("ldmatrix.sync.aligned.m8n8.x4.shared.b16 {%0,%1,%2,%3}, [%4];"
                 : "=r"(r0), "=r"(r1), "=r"(r2), "=r"(r3) : "r"(addr));
}

__device__ __forceinline__ float blockSum(float v, float* sh) {
    __syncthreads();
    int lane = threadIdx.x & 31, w = threadIdx.x >> 5;
#pragma unroll
    for (int o = 16; o; o >>= 1) v += __shfl_xor_sync(0xffffffffu, v, o);
    if (lane == 0) sh[w] = v;
    __syncthreads();
    if (threadIdx.x == 0) {
        float s = 0.f; int nw = blockDim.x >> 5;
        for (int i = 0; i < nw; i++) s += sh[i];
        sh[32] = s;
    }
    __syncthreads();
    return sh[32];
}

__device__ __forceinline__ float blockMax(float v, float* sh) {
    __syncthreads();
    int lane = threadIdx.x & 31, w = threadIdx.x >> 5;
#pragma unroll
    for (int o = 16; o; o >>= 1) v = fmaxf(v, __shfl_xor_sync(0xffffffffu, v, o));
    if (lane == 0) sh[w] = v;
    __syncthreads();
    if (threadIdx.x == 0) {
        float s = -3.4e38f; int nw = blockDim.x >> 5;
        for (int i = 0; i < nw; i++) s = fmaxf(s, sh[i]);
        sh[32] = s;
    }
    __syncthreads();
    return sh[32];
}

// ---------------- split-bf16 tensor-core GEMM -----------------------------------
// A: [M,K] hi/lo bf16 k-contiguous; B: [N,K] hi/lo bf16. C = A·B^T.
// ONETERM=false: 3-term compensation (hh + hl + lh) => ~fp32 accuracy.
// ONETERM=true : hh only (approximate, for ranking).
// AIDX: A-rows gathered via rowlist; dynamic M via *cntp with block early-exit.
// XROW: blockIdx.x indexes rows (fast-varying) -> wave shares B tiles in L2
//       (use when N >> M, e.g. the scores GEMM). Grid must be (M/128, N/128).
// Block 128x128, K-chunk 32, 3 stages, one barrier per chunk, 8 warps 2(M)x4(N).
// MODE 0: +bias   MODE 1: relu(+bias)   MODE 2: +bias+res
// MODE 3: colv[n]-2*AB -> bf16 key into Chi (ranking only)
// MODE 4: AB+res+rowv[m]*bias[n]+colv[n]
// RESSPLIT: res from bf16 hi/lo pair.  DONORM: atomicAdd row sumsq->normout.
#define GS_STAGE 32768                   // 4 buffers x 8KB
#define GS_SMEM  (3 * GS_STAGE)

template<int MODE, bool WF32, bool WSPLIT, bool RESSPLIT, bool DONORM, bool ONETERM,
         bool AIDX, bool XROW>
__global__ void __launch_bounds__(256, 2) gemm_bf16s_k(
    int M, int N, int K,
    const bf16* __restrict__ Ahg, const bf16* __restrict__ Alg,
    const bf16* __restrict__ Bhg, const bf16* __restrict__ Blg,
    const float* __restrict__ bias, const float* __restrict__ res,
    const bf16* __restrict__ resbh, const bf16* __restrict__ resbl,
    const float* __restrict__ rowv, const float* __restrict__ colv,
    float* __restrict__ C, bf16* __restrict__ Chi, bf16* __restrict__ Clo,
    float* __restrict__ normout,
    const int* __restrict__ rowlist, const int* __restrict__ cntp)
{
    extern __shared__ __align__(1024) char smem[];
    const unsigned sbase = (unsigned)__cvta_generic_to_shared(smem);

    const int tid  = threadIdx.x;
    const int lane = tid & 31;
    const int wid  = tid >> 5;
    const int wm   = (wid & 1) * 64;
    const int wn   = (wid >> 1) * 32;
    const int grp  = lane >> 2;
    const int thr  = lane & 3;

    const long rowBase = XROW ? (long)blockIdx.x * 128 : (long)blockIdx.y * 128;
    const long colBase = XROW ? (long)blockIdx.y * 128 : (long)blockIdx.x * 128;

    if (AIDX) {
        if (rowBase >= (long)*cntp) return;    // dynamic M early-exit
    }

    // A-row source indices for this thread's two fill rows
    long arow1, arow2;
    {
        const int r1 = tid >> 2, r2 = (tid >> 2) + 64;
        if (AIDX) {
            arow1 = rowlist[rowBase + r1];
            arow2 = rowlist[rowBase + r2];
        } else {
            arow1 = rowBase + r1;
            arow2 = rowBase + r2;
        }
    }

    float acc[4][4][4];
#pragma unroll
    for (int mi = 0; mi < 4; mi++)
#pragma unroll
        for (int ni = 0; ni < 4; ni++)
#pragma unroll
            for (int j = 0; j < 4; j++) acc[mi][ni][j] = 0.f;

    const int T = K >> 5;    // 32-elem chunks

    auto fill = [&](int s, int t) {
        const int k0 = t << 5;
        const unsigned sb = sbase + (unsigned)s * GS_STAGE;
#pragma unroll
        for (int i = 0; i < 2; i++) {
            int q = tid + i * 256;
            int r = q >> 2, c = q & 3;
            int off = r * 64 + c * 16;
            int sw  = off ^ ((off >> 3) & 0x30);
            const long arow = i ? arow2 : arow1;
            const long ao = arow * (long)K + k0 + c * 8;
            const long bo = (colBase + r) * (long)K + k0 + c * 8;
            cp16s(sb + sw,          Ahg + ao);
            cp16s(sb + 16384 + sw,  Bhg + bo);
            if (!ONETERM) {
                cp16s(sb + 8192 + sw,   Alg + ao);
                cp16s(sb + 24576 + sw,  Blg + bo);
            }
        }
        asm volatile("cp.async.commit_group;" ::: "memory");
    };

    const int aRow16 = lane & 15;
    const int aKx    = (lane & 16) ? 16 : 0;
    const int bRowO  = (lane & 7) + ((lane & 16) ? 8 : 0);
    const int bKx    = (lane & 8) ? 16 : 0;

    fill(0, 0);
    if (T > 1) fill(1, 1);

    for (int t = 0; t < T; t++) {
        if (t < T - 1) asm volatile("cp.async.wait_group 1;" ::: "memory");
        else           asm volatile("cp.async.wait_group 0;" ::: "memory");
        __syncthreads();
        if (t + 2 < T) fill((t + 2) % 3, t + 2);

        const unsigned ab  = sbase + (unsigned)(t % 3) * GS_STAGE;
        const unsigned alb = ab + 8192, bb = ab + 16384, blb = ab + 24576;

#pragma unroll
        for (int s16 = 0; s16 < 64; s16 += 32) {
            unsigned ah[4][4], al[4][4];
#pragma unroll
            for (int mi = 0; mi < 4; mi++) {
                int rowb = (wm + mi * 16 + aRow16) * 64;
                unsigned msk = (unsigned)((rowb >> 3) & 0x30);
                ldsm4(ah[mi][0], ah[mi][1], ah[mi][2], ah[mi][3],
                      (ab + rowb + s16 + aKx) ^ msk);
                if (!ONETERM)
                    ldsm4(al[mi][0], al[mi][1], al[mi][2], al[mi][3],
                          (alb + rowb + s16 + aKx) ^ msk);
            }
#pragma unroll
            for (int p = 0; p < 2; p++) {
                int rowb = (wn + p * 16 + bRowO) * 64;
                unsigned msk = (unsigned)((rowb >> 3) & 0x30);
                unsigned bh[4], bl[4];
                ldsm4(bh[0], bh[1], bh[2], bh[3], (bb + rowb + s16 + bKx) ^ msk);
                if (!ONETERM)
                    ldsm4(bl[0], bl[1], bl[2], bl[3], (blb + rowb + s16 + bKx) ^ msk);
                // term-major: 8 independent MMAs between same-acc reuses
#pragma unroll
                for (int mi = 0; mi < 4; mi++) {
                    mma_bf16(acc[mi][2 * p],     ah[mi], &bh[0]);
                    mma_bf16(acc[mi][2 * p + 1], ah[mi], &bh[2]);
                }
                if (!ONETERM) {
#pragma unroll
                    for (int mi = 0; mi < 4; mi++) {
                        mma_bf16(acc[mi][2 * p],     ah[mi], &bl[0]);
                        mma_bf16(acc[mi][2 * p + 1], ah[mi], &bl[2]);
                    }
#pragma unroll
                    for (int mi = 0; mi < 4; mi++) {
                        mma_bf16(acc[mi][2 * p],     al[mi], &bh[0]);
                        mma_bf16(acc[mi][2 * p + 1], al[mi], &bh[2]);
                    }
                }
            }
        }
    }

    // ---- epilogue ----------------------------------------------------------
#pragma unroll
    for (int mi = 0; mi < 4; mi++) {
#pragma unroll
        for (int half = 0; half < 2; half++) {
            const long rr = rowBase + wm + mi * 16 + grp + half * 8;
            const float rv = (MODE == 4) ? rowv[rr] : 0.f;
            float ss = 0.f;
#pragma unroll
            for (int ni = 0; ni < 4; ni++) {
                const long c = colBase + wn + ni * 8 + thr * 2;
                float o0 = acc[mi][ni][half * 2 + 0];
                float o1 = acc[mi][ni][half * 2 + 1];
                if (MODE == 0 || MODE == 1 || MODE == 2) {
                    if (bias) { o0 += bias[c]; o1 += bias[c + 1]; }
                }
                if (MODE == 2) {
                    if (RESSPLIT) {
                        ushort2 rh = *(const ushort2*)&resbh[rr * N + c];
                        ushort2 rl = *(const ushort2*)&resbl[rr * N + c];
                        o0 += __bfloat162float(__ushort_as_bfloat16(rh.x))
                            + __bfloat162float(__ushort_as_bfloat16(rl.x));
                        o1 += __bfloat162float(__ushort_as_bfloat16(rh.y))
                            + __bfloat162float(__ushort_as_bfloat16(rl.y));
                    } else {
                        o0 += res[rr * N + c]; o1 += res[rr * N + c + 1];
                    }
                }
                if (MODE == 1) { o0 = fmaxf(o0, 0.f); o1 = fmaxf(o1, 0.f); }
                if (MODE == 3) {
                    o0 = colv[c]     - 2.f * o0;
                    o1 = colv[c + 1] - 2.f * o1;
                    ushort2 kk;
                    kk.x = __bfloat16_as_ushort(__float2bfloat16_rn(o0));
                    kk.y = __bfloat16_as_ushort(__float2bfloat16_rn(o1));
                    *(ushort2*)&Chi[rr * N + c] = kk;
                }
                if (MODE == 4) {
                    o0 = o0 + res[rr * N + c]     + rv * bias[c]     + colv[c];
                    o1 = o1 + res[rr * N + c + 1] + rv * bias[c + 1] + colv[c + 1];
                }
                if (DONORM) ss += o0 * o0 + o1 * o1;
                if (WF32)
                    *(float2*)(C + rr * N + c) = make_float2(o0, o1);
                if (WSPLIT) {
                    bf16 h0, l0, h1, l1;
                    split1(o0, h0, l0);
                    split1(o1, h1, l1);
                    ushort2 hp, lp;
                    hp.x = __bfloat16_as_ushort(h0); hp.y = __bfloat16_as_ushort(h1);
                    lp.x = __bfloat16_as_ushort(l0); lp.y = __bfloat16_as_ushort(l1);
                    *(ushort2*)&Chi[rr * N + c] = hp;
                    *(ushort2*)&Clo[rr * N + c] = lp;
                }
            }
            if (DONORM) {
                ss += __shfl_xor_sync(0xffffffffu, ss, 1);
                ss += __shfl_xor_sync(0xffffffffu, ss, 2);
                if (thr == 0) atomicAdd(normout + rr, ss);
            }
        }
    }
}

// ---------------- init: norms, flags, compact list ------------------------------
__global__ void initsel_k(float* cnorm, int* flags, int* list, int* cnt)
{
    int i = blockIdx.x * 256 + threadIdx.x;
    if (i < NT)  cnorm[i] = 0.f;
    if (i < NC)  flags[i] = 0;
    if (i < NT)  list[i] = (i < BSZ) ? (NC + i) : 0;
    if (i == 0)  cnt[0] = BSZ;
}

// ---------------- mark used candidates, build compact list ----------------------
__global__ void mark_k(const int* __restrict__ idx, int* flags, int* remap,
                       int* list, int* cnt)
{
    int e = blockIdx.x * 256 + threadIdx.x;
    if (e >= BSZ * CC) return;
    int i = idx[e];
    if (atomicExch(&flags[i], 1) == 0) {
        int s = atomicAdd(cnt, 1);
        remap[i] = s;
        list[s] = i;
    }
}

// ---------------- split fp32 -> bf16 hi/lo (same layout) -----------------------
__global__ void split4_k(const float* __restrict__ in, bf16* __restrict__ oh,
                         bf16* __restrict__ ol, long n)
{
    long i = ((long)blockIdx.x * blockDim.x + threadIdx.x) * 4;
    if (i >= n) return;
    float4 v = *(const float4*)(in + i);
    bf16 h0,l0,h1,l1,h2,l2,h3,l3;
    split1(v.x,h0,l0); split1(v.y,h1,l1); split1(v.z,h2,l2); split1(v.w,h3,l3);
    ushort4 hp, lp;
    hp.x=__bfloat16_as_ushort(h0); hp.y=__bfloat16_as_ushort(h1);
    hp.z=__bfloat16_as_ushort(h2); hp.w=__bfloat16_as_ushort(h3);
    lp.x=__bfloat16_as_ushort(l0); lp.y=__bfloat16_as_ushort(l1);
    lp.z=__bfloat16_as_ushort(l2); lp.w=__bfloat16_as_ushort(l3);
    *(ushort4*)&oh[i] = hp;
    *(ushort4*)&ol[i] = lp;
}

// ---------------- weight split + transpose: [K,N] fp32 -> [N,K] bf16 hi/lo -----
__global__ void wsplitT_k(const float* __restrict__ in, int K, int N,
                          bf16* __restrict__ oh, bf16* __restrict__ ol)
{
    __shared__ float tile[32][33];
    int n0 = blockIdx.x * 32, k0 = blockIdx.y * 32;
    int tx = threadIdx.x, ty = threadIdx.y;   // 32 x 8
#pragma unroll
    for (int j = 0; j < 4; j++)
        tile[ty + j * 8][tx] = in[(long)(k0 + ty + j * 8) * N + n0 + tx];
    __syncthreads();
#pragma unroll
    for (int j = 0; j < 4; j++) {
        float v = tile[tx][ty + j * 8];
        bf16 h, l; split1(v, h, l);
        long o = (long)(n0 + ty + j * 8) * K + k0 + tx;
        oh[o] = h; ol[o] = l;
    }
}

// ------- warp-per-row layernorm (width 512) -> split bf16, no block syncs -------
__global__ void ln512w_split_k(const float* __restrict__ in, const float* __restrict__ g,
                               const float* __restrict__ b,
                               bf16* __restrict__ oh, bf16* __restrict__ ol)
{
    const int warp = threadIdx.x >> 5, lane = threadIdx.x & 31;
    const long row = (long)blockIdx.x * 8 + warp;
    const float* x = in + row * DD;

    float4 v[4];
    float s = 0.f;
#pragma unroll
    for (int j = 0; j < 4; j++) {
        v[j] = *(const float4*)(x + (lane + 32 * j) * 4);
        s += v[j].x + v[j].y + v[j].z + v[j].w;
    }
#pragma unroll
    for (int o = 16; o; o >>= 1) s += __shfl_xor_sync(0xffffffffu, s, o);
    const float m = s * (1.f / DD);

    float var = 0.f;
#pragma unroll
    for (int j = 0; j < 4; j++) {
        v[j].x -= m; v[j].y -= m; v[j].z -= m; v[j].w -= m;
        var += v[j].x * v[j].x + v[j].y * v[j].y + v[j].z * v[j].z + v[j].w * v[j].w;
    }
#pragma unroll
    for (int o = 16; o; o >>= 1) var += __shfl_xor_sync(0xffffffffu, var, o);
    const float inv = rsqrtf(var * (1.f / DD) + 1e-5f);

#pragma unroll
    for (int j = 0; j < 4; j++) {
        const int c = (lane + 32 * j) * 4;
        float4 gg = *(const float4*)(g + c);
        float4 bb = *(const float4*)(b + c);
        float o0 = v[j].x * inv * gg.x + bb.x;
        float o1 = v[j].y * inv * gg.y + bb.y;
        float o2 = v[j].z * inv * gg.z + bb.z;
        float o3 = v[j].w * inv * gg.w + bb.w;
        bf16 h0,l0,h1,l1,h2,l2,h3,l3;
        split1(o0,h0,l0); split1(o1,h1,l1); split1(o2,h2,l2); split1(o3,h3,l3);
        ushort4 hp, lp;
        hp.x=__bfloat16_as_ushort(h0); hp.y=__bfloat16_as_ushort(h1);
        hp.z=__bfloat16_as_ushort(h2); hp.w=__bfloat16_as_ushort(h3);
        lp.x=__bfloat16_as_ushort(l0); lp.y=__bfloat16_as_ushort(l1);
        lp.z=__bfloat16_as_ushort(l2); lp.w=__bfloat16_as_ushort(l3);
        *(ushort4*)&oh[row * DD + c] = hp;
        *(ushort4*)&ol[row * DD + c] = lp;
    }
}

// -------- top-96 on bf16 keys: 2-level 8-bit compacting radix select -----------
__device__ __forceinline__ unsigned fkey16(unsigned u) {
    return (u & 0x8000u) ? (~u & 0xFFFFu) : (u | 0x8000u);
}

__global__ void topk96b_k(const unsigned short* __restrict__ keys,
                          unsigned* __restrict__ bufA, int* __restrict__ idxo)
{
    const int b = blockIdx.x, tid = threadIdx.x;   // 256 threads
    const unsigned short* row = keys + (long)b * NC;
    unsigned* A = bufA + (long)b * NC;
    int* out = idxo + b * CC;

    __shared__ int hist[256];
    __shared__ int s_fill, s_cnt, s_bucket, s_need;

    hist[tid] = 0;
    if (tid == 0) { s_fill = 0; s_cnt = 0; }
    __syncthreads();

    const uint4* row4 = (const uint4*)row;
    for (int i = tid; i < NC / 8; i += 256) {
        uint4 v = row4[i];
        unsigned w[4] = {v.x, v.y, v.z, v.w};
#pragma unroll
        for (int j = 0; j < 4; j++) {
            atomicAdd(&hist[fkey16(w[j] & 0xFFFFu) >> 8], 1);
            atomicAdd(&hist[fkey16(w[j] >> 16) >> 8], 1);
        }
    }
    __syncthreads();
    if (tid == 0) {
        int cum = 0;
        for (int bin = 0; bin < 256; bin++) {
            int h = hist[bin];
            if (cum + h >= CC) { s_bucket = bin; s_need = CC - cum; break; }
            cum += h;
        }
    }
    __syncthreads();
    const unsigned b0 = (unsigned)s_bucket;
    for (int i = tid; i < NC; i += 256) {
        unsigned k = fkey16((unsigned)row[i]);
        unsigned hb = k >> 8;
        if (hb < b0)       out[atomicAdd(&s_fill, 1)] = i;
        else if (hb == b0) A[atomicAdd(&s_cnt, 1)] = (k << 16) | (unsigned)i;
    }
    __syncthreads();
    const int m = s_cnt;

    hist[tid] = 0;
    __syncthreads();
    for (int i = tid; i < m; i += 256)
        atomicAdd(&hist[(A[i] >> 16) & 0xFFu], 1);
    __syncthreads();
    if (tid == 0) {
        int cum = 0, need = s_need;
        for (int bin = 0; bin < 256; bin++) {
            int h = hist[bin];
            if (cum + h >= need) { s_bucket = bin; break; }
            cum += h;
        }
    }
    __syncthreads();
    const unsigned b1 = (unsigned)s_bucket;
    for (int i = tid; i < m; i += 256) {
        unsigned e = A[i];
        if (((e >> 16) & 0xFFu) < b1)
            out[atomicAdd(&s_fill, 1)] = (int)(e & 0xFFFFu);
    }
    __syncthreads();
    for (int i = tid; i < m; i += 256) {
        unsigned e = A[i];
        if (((e >> 16) & 0xFFu) == b1) {
            int p = atomicAdd(&s_fill, 1);
            if (p < CC) out[p] = (int)(e & 0xFFFFu);
        }
    }
}

// ------- exact rescore of the 96 selected + softmax + ybar ----------------------
__global__ void rescore96_k(const bf16* __restrict__ kxh, const bf16* __restrict__ kxl,
                            const bf16* __restrict__ kh,  const bf16* __restrict__ kl,
                            const float* __restrict__ cnorm, const int* __restrict__ idx,
                            const float* __restrict__ cy,
                            float* __restrict__ probs, float* __restrict__ ybar)
{
    const int b = blockIdx.x, tid = threadIdx.x;   // 256 threads, 8 warps
    const int warp = tid >> 5, lane = tid & 31;
    __shared__ float q[DD];
    __shared__ float sims[CC];
    __shared__ int   sidx[CC];
    __shared__ float sh[33];

    for (int i = tid; i < DD; i += 256)
        q[i] = __bfloat162float(kxh[(long)b * DD + i]) +
               __bfloat162float(kxl[(long)b * DD + i]);
    if (tid < CC) sidx[tid] = idx[b * CC + tid];
    __syncthreads();

    for (int c = warp; c < CC; c += 8) {
        const long base = (long)sidx[c] * DD + lane * 16;
        uint4 h0 = *(const uint4*)(kh + base);
        uint4 h1 = *(const uint4*)(kh + base + 8);
        uint4 l0 = *(const uint4*)(kl + base);
        uint4 l1 = *(const uint4*)(kl + base + 8);
        const unsigned hw[8] = {h0.x, h0.y, h0.z, h0.w, h1.x, h1.y, h1.z, h1.w};
        const unsigned lw[8] = {l0.x, l0.y, l0.z, l0.w, l1.x, l1.y, l1.z, l1.w};
        float dot = 0.f;
#pragma unroll
        for (int j = 0; j < 8; j++) {
            float c0 = __bfloat162float(__ushort_as_bfloat16((unsigned short)(hw[j] & 0xFFFF)))
                     + __bfloat162float(__ushort_as_bfloat16((unsigned short)(lw[j] & 0xFFFF)));
            float c1 = __bfloat162float(__ushort_as_bfloat16((unsigned short)(hw[j] >> 16)))
                     + __bfloat162float(__ushort_as_bfloat16((unsigned short)(lw[j] >> 16)));
            dot += q[lane * 16 + 2 * j] * c0 + q[lane * 16 + 2 * j + 1] * c1;
        }
#pragma unroll
        for (int o = 16; o; o >>= 1) dot += __shfl_xor_sync(0xffffffffu, dot, o);
        if (lane == 0) sims[c] = 2.f * dot - cnorm[sidx[c]];
    }
    __syncthreads();

    float sim = (tid < CC) ? sims[tid] : -3.4e38f;
    float mx = blockMax(sim, sh);
    float e = (tid < CC) ? expf(sim - mx) : 0.f;
    float s = blockSum(e, sh);
    float p = e / s;
    if (tid < CC) probs[b * CC + tid] = p;
    float yv = (tid < CC) ? p * cy[sidx[tid]] : 0.f;
    float yb = blockSum(yv, sh);
    if (tid == 0) ybar[b] = yb;
}

// ---- s[b,:] = sum_c probs * relu(kproj + T_b1 - cproj[remap[idx]]) -------------
__global__ void ctxsum_split_k(const float* __restrict__ cproj,
                               const float* __restrict__ tb1,
                               const int* __restrict__ idx, const int* __restrict__ remap,
                               const float* __restrict__ probs,
                               bf16* __restrict__ oh, bf16* __restrict__ ol)
{
    const int b = blockIdx.x, j = threadIdx.x;   // 1024 threads
    __shared__ int   si[CC];
    __shared__ float sp[CC];
    if (j < CC) { si[j] = remap[idx[b * CC + j]]; sp[j] = probs[b * CC + j]; }
    __syncthreads();
    float kp = cproj[(long)b * DBD + j] + tb1[j];    // queries occupy slots 0..BSZ
    float acc = 0.f;
#pragma unroll 4
    for (int c = 0; c < CC; c++) {
        float v = kp - cproj[(long)si[c] * DBD + j];
        acc += sp[c] * fmaxf(v, 0.f);
    }
    bf16 h, l; split1(acc, h, l);
    oh[(long)b * DBD + j] = h;
    ol[(long)b * DBD + j] = l;
}

// ---------------- head: relu(ln(x)) @ h_W + h_b ---------------------------------
__global__ void head512_k(const float* __restrict__ in, const float* __restrict__ g,
                          const float* __restrict__ bb, const float* __restrict__ hW,
                          const float* __restrict__ hb, float* __restrict__ out)
{
    __shared__ float sh[33];
    const long row = blockIdx.x;
    const float* x = in + row * DD;
    int t = threadIdx.x;
    float a = x[t], c = x[t + 256];
    float m = blockSum(a + c, sh) * (1.f / DD);
    float d0 = a - m, d1 = c - m;
    float v = blockSum(d0 * d0 + d1 * d1, sh) * (1.f / DD);
    float inv = rsqrtf(v + 1e-5f);
    float s0 = fmaxf(d0 * inv * g[t] + bb[t], 0.f) * hW[t];
    float s1 = fmaxf(d1 * inv * g[t + 256] + bb[t + 256], 0.f) * hW[t + 256];
    float tot = blockSum(s0 + s1, sh);
    if (t == 0) out[row] = tot + hb[0];
}

// ---------------- host side -----------------------------------------------------
template<typename T>
static T* devptr(const void* sym) {
    void* p = nullptr;
    cudaGetSymbolAddress(&p, sym);
    return (T*)p;
}

template<int MODE, bool WF32, bool WSPLIT, bool RESSPLIT, bool DONORM, bool ONETERM,
         bool AIDX = false, bool XROW = false>
static void launch_gemm(int M, int N, int K,
                        const bf16* Ah, const bf16* Al, const bf16* Bh, const bf16* Bl,
                        const float* bias, const float* res,
                        const bf16* resbh, const bf16* resbl,
                        const float* rowv, const float* colv,
                        float* C, bf16* Chi, bf16* Clo, float* normout,
                        const int* rowlist = nullptr, const int* cntp = nullptr) {
    cudaFuncSetAttribute(gemm_bf16s_k<MODE, WF32, WSPLIT, RESSPLIT, DONORM, ONETERM, AIDX, XROW>,
                         cudaFuncAttributeMaxDynamicSharedMemorySize, GS_SMEM);
    dim3 grid = XROW ? dim3(M / 128, N / 128) : dim3(N / 128, M / 128);
    gemm_bf16s_k<MODE, WF32, WSPLIT, RESSPLIT, DONORM, ONETERM, AIDX, XROW><<<grid, 256, GS_SMEM>>>(
        M, N, K, Ah, Al, Bh, Bl, bias, res, resbh, resbl, rowv, colv,
        C, Chi, Clo, normout, rowlist, cntp);
}

extern "C" void kernel_launch(void* const* d_in, const int* in_sizes, int n_in,
                              void* d_out, int out_size)
{
    const float* x_num  = (const float*)d_in[0];
    const float* cand   = (const float*)d_in[1];
    const float* cy     = (const float*)d_in[2];
    const float* lin_W  = (const float*)d_in[3];
    const float* lin_b  = (const float*)d_in[4];
    const float* e_W1   = (const float*)d_in[5];
    const float* e_b1   = (const float*)d_in[6];
    const float* e_W2   = (const float*)d_in[7];
    const float* e_b2   = (const float*)d_in[8];
    const float* mix_g  = (const float*)d_in[9];
    const float* mix_b  = (const float*)d_in[10];
    const float* K_W    = (const float*)d_in[11];
    const float* K_b    = (const float*)d_in[12];
    const float* lab_W  = (const float*)d_in[13];
    const float* lab_b  = (const float*)d_in[14];
    const float* T_W1   = (const float*)d_in[15];
    const float* T_b1   = (const float*)d_in[16];
    const float* T_W2   = (const float*)d_in[17];
    const float* p_ln_g = (const float*)d_in[18];
    const float* p_ln_b = (const float*)d_in[19];
    const float* p_W1   = (const float*)d_in[20];
    const float* p_b1   = (const float*)d_in[21];
    const float* p_W2   = (const float*)d_in[22];
    const float* p_b2   = (const float*)d_in[23];
    const float* h_ln_g = (const float*)d_in[24];
    const float* h_ln_b = (const float*)d_in[25];
    const float* h_W    = (const float*)d_in[26];
    const float* h_b    = (const float*)d_in[27];
    float* out = (float*)d_out;

    float* p_h     = devptr<float>(g_h);
    float* p_cproj = devptr<float>(g_cproj);
    float* p_cnorm = devptr<float>(g_cnorm);
    unsigned short* p_keys = devptr<unsigned short>(g_keys);
    unsigned* p_bufA = devptr<unsigned>(g_bufA);
    int*   p_idx   = devptr<int>(g_idx);
    float* p_probs = devptr<float>(g_probs);
    float* p_ybar  = devptr<float>(g_ybar);
    float* p_x2    = devptr<float>(g_x2);
    float* p_x3    = devptr<float>(g_x3);
    int* p_flags = devptr<int>(g_flags);
    int* p_remap = devptr<int>(g_remap);
    int* p_list  = devptr<int>(g_list);
    int* p_cnt   = devptr<int>(g_cnt);

    bf16 *candh = devptr<bf16>(g_candh), *candl = devptr<bf16>(g_candl);
    bf16 *hh = devptr<bf16>(g_hh),   *hl = devptr<bf16>(g_hl);
    bf16 *th = devptr<bf16>(g_th),   *tl = devptr<bf16>(g_tl);
    bf16 *hnh = devptr<bf16>(g_hnh), *hnl = devptr<bf16>(g_hnl);
    bf16 *kh = devptr<bf16>(g_kh),   *kl = devptr<bf16>(g_kl);
    bf16 *xnh = devptr<bf16>(g_xnh), *xnl = devptr<bf16>(g_xnl);
    bf16 *sh_ = devptr<bf16>(g_sh),  *sl_ = devptr<bf16>(g_sl);

    bf16 *wlinh = devptr<bf16>(g_wlinh), *wlinl = devptr<bf16>(g_wlinl);
    bf16 *we1h = devptr<bf16>(g_we1h),   *we1l = devptr<bf16>(g_we1l);
    bf16 *we2h = devptr<bf16>(g_we2h),   *we2l = devptr<bf16>(g_we2l);
    bf16 *wKh = devptr<bf16>(g_wKh),     *wKl = devptr<bf16>(g_wKl);
    bf16 *wT1h = devptr<bf16>(g_wT1h),   *wT1l = devptr<bf16>(g_wT1l);
    bf16 *wT2h = devptr<bf16>(g_wT2h),   *wT2l = devptr<bf16>(g_wT2l);
    bf16 *wp1h = devptr<bf16>(g_wp1h),   *wp1l = devptr<bf16>(g_wp1l);
    bf16 *wp2h = devptr<bf16>(g_wp2h),   *wp2l = devptr<bf16>(g_wp2l);

    // merged-row views (query rows appended after candidate rows)
    bf16 *kqh = kh + (long)NC * DD, *kql = kl + (long)NC * DD;   // query k
    float* p_hx = p_h + (long)NC * DD;                           // query encoder out

    // ---- one-time prep ------------------------------------------------------
    split4_k<<<(NC * FD / 4 + 255) / 256, 256>>>(cand, candh, candl, (long)NC * FD);
    split4_k<<<(BSZ * FD / 4 + 255) / 256, 256>>>(x_num, candh + (long)NC * FD,
                                                  candl + (long)NC * FD, (long)BSZ * FD);
    initsel_k<<<(NT + 255) / 256, 256>>>(p_cnorm, p_flags, p_list, p_cnt);
    {
        dim3 blk(32, 8);
        wsplitT_k<<<dim3(DD / 32, FD / 32), blk>>>(lin_W, FD, DD, wlinh, wlinl);
        wsplitT_k<<<dim3(DBD / 32, DD / 32), blk>>>(e_W1, DD, DBD, we1h, we1l);
        wsplitT_k<<<dim3(DD / 32, DBD / 32), blk>>>(e_W2, DBD, DD, we2h, we2l);
        wsplitT_k<<<dim3(DD / 32, DD / 32), blk>>>(K_W, DD, DD, wKh, wKl);
        wsplitT_k<<<dim3(DBD / 32, DD / 32), blk>>>(T_W1, DD, DBD, wT1h, wT1l);
        wsplitT_k<<<dim3(DD / 32, DBD / 32), blk>>>(T_W2, DBD, DD, wT2h, wT2l);
        wsplitT_k<<<dim3(DBD / 32, DD / 32), blk>>>(p_W1, DD, DBD, wp1h, wp1l);
        wsplitT_k<<<dim3(DD / 32, DBD / 32), blk>>>(p_W2, DBD, DD, wp2h, wp2l);
    }

    // ---- merged encoder (candidates + queries in one chain) ------------------
    launch_gemm<0, false, true, false, false, false>(NT, DD, FD, candh, candl, wlinh, wlinl,
        lin_b, nullptr, nullptr, nullptr, nullptr, nullptr, nullptr, hh, hl, nullptr);
    launch_gemm<1, false, true, false, false, false>(NT, DBD, DD, hh, hl, we1h, we1l,
        e_b1, nullptr, nullptr, nullptr, nullptr, nullptr, nullptr, th, tl, nullptr);
    launch_gemm<2, true, false, true, false, false>(NT, DD, DBD, th, tl, we2h, we2l,
        e_b2, nullptr, hh, hl, nullptr, nullptr, p_h, nullptr, nullptr, nullptr);
    ln512w_split_k<<<NT / 8, 256>>>(p_h, mix_g, mix_b, hnh, hnl);
    launch_gemm<0, false, true, false, true, false>(NT, DD, DD, hnh, hnl, wKh, wKl,
        K_b, nullptr, nullptr, nullptr, nullptr, nullptr, nullptr, kh, kl, p_cnorm);

    // ---- kNN: approx bf16 ranking keys (XROW: B tiles L2-shared) --------------
    launch_gemm<3, false, false, false, false, true, false, true>(BSZ, NC, DD, kqh, kql, kh, kl,
        nullptr, nullptr, nullptr, nullptr, nullptr, p_cnorm, nullptr,
        (bf16*)p_keys, nullptr, nullptr);
    topk96b_k<<<BSZ, 256>>>(p_keys, p_bufA, p_idx);
    rescore96_k<<<BSZ, 256>>>(kqh, kql, kh, kl, p_cnorm, p_idx, cy, p_probs, p_ybar);

    // ---- T1 projection over [queries | used candidates] only -----------------
    mark_k<<<(BSZ * CC + 255) / 256, 256>>>(p_idx, p_flags, p_remap, p_list, p_cnt);
    launch_gemm<0, true, false, false, false, false, true>(NT, DBD, DD, kh, kl, wT1h, wT1l,
        nullptr, nullptr, nullptr, nullptr, nullptr, nullptr, p_cproj, nullptr, nullptr, nullptr,
        p_list, p_cnt);

    // ---- context aggregation ----------------------------------------------
    ctxsum_split_k<<<BSZ, 1024>>>(p_cproj, T_b1, p_idx, p_remap, p_probs, sh_, sl_);
    launch_gemm<4, true, false, false, false, false>(BSZ, DD, DBD, sh_, sl_, wT2h, wT2l,
        lab_W, p_hx, nullptr, nullptr, p_ybar, lab_b, p_x2, nullptr, nullptr, nullptr);

    // ---- predictor block + head -------------------------------------------
    ln512w_split_k<<<BSZ / 8, 256>>>(p_x2, p_ln_g, p_ln_b, xnh, xnl);
    launch_gemm<1, false, true, false, false, false>(BSZ, DBD, DD, xnh, xnl, wp1h, wp1l,
        p_b1, nullptr, nullptr, nullptr, nullptr, nullptr, nullptr, th, tl, nullptr);
    launch_gemm<2, true, false, false, false, false>(BSZ, DD, DBD, th, tl, wp2h, wp2l,
        p_b2, p_x2, nullptr, nullptr, nullptr, nullptr, p_x3, nullptr, nullptr, nullptr);
    head512_k<<<BSZ, 256>>>(p_x3, h_ln_g, h_ln_b, h_W, h_b, out);

    (void)in_sizes; (void)n_in; (void)out_size;
}

// round 17
// speedup vs baseline: 1.0162x; 1.0162x over previous
#include <cuda_runtime.h>
#include <cuda_bf16.h>
#include <cstdint>

// Problem constants (fixed by the dataset)
#define NC  65536   // candidates
#define BSZ 1024    // batch
#define NT  (NC+BSZ) // merged encoder rows (66560 = 520*128)
#define FD  64      // input features
#define DD  512     // model dim
#define DBD 1024    // hidden dim
#define CC  96      // context size

typedef __nv_bfloat16 bf16;

// ---------------- device scratch (allocation-free rule: __device__ globals) ----
__device__ float g_h    [(long)NT*DD];     // encoder residual out (fp32)
__device__ float g_cproj[(long)NT*DBD];    // compact: [queries | used candidates]
__device__ float g_cnorm[NT];
__device__ unsigned short g_keys[(long)BSZ*NC];  // bf16 ranking keys
__device__ unsigned g_bufA[(long)BSZ*NC];        // top-k compaction
__device__ int   g_idx  [BSZ*CC];
__device__ float g_probs[BSZ*CC];
__device__ float g_ybar [BSZ];
__device__ float g_x2   [BSZ*DD];
__device__ float g_x3   [BSZ*DD];

// used-candidate compaction
__device__ int g_flags[NC];
__device__ int g_remap[NC];
__device__ int g_list [NT];
__device__ int g_cnt  [1];

// split bf16 activation buffers (hi/lo), merged cand+query rows
__device__ bf16 g_candh[(long)NT*FD],  g_candl[(long)NT*FD];
__device__ bf16 g_hh   [(long)NT*DD],  g_hl   [(long)NT*DD];
__device__ bf16 g_th   [(long)NT*DBD], g_tl   [(long)NT*DBD];
__device__ bf16 g_hnh  [(long)NT*DD],  g_hnl  [(long)NT*DD];
__device__ bf16 g_kh   [(long)NT*DD],  g_kl   [(long)NT*DD];
__device__ bf16 g_xnh  [BSZ*DD],  g_xnl  [BSZ*DD];
__device__ bf16 g_sh   [BSZ*DBD], g_sl   [BSZ*DBD];

// split + transposed weights [N,K]
__device__ bf16 g_wlinh[DD*FD],   g_wlinl[DD*FD];
__device__ bf16 g_we1h [DBD*DD],  g_we1l [DBD*DD];
__device__ bf16 g_we2h [DD*DBD],  g_we2l [DD*DBD];
__device__ bf16 g_wKh  [DD*DD],   g_wKl  [DD*DD];
__device__ bf16 g_wT1h [DBD*DD],  g_wT1l [DBD*DD];
__device__ bf16 g_wT2h [DD*DBD],  g_wT2l [DD*DBD];
__device__ bf16 g_wp1h [DBD*DD],  g_wp1l [DBD*DD];
__device__ bf16 g_wp2h [DD*DBD],  g_wp2l [DD*DBD];

// ---------------- helpers -------------------------------------------------------
__device__ __forceinline__ void split1(float x, bf16 &h, bf16 &l) {
    h = __float2bfloat16_rn(x);
    l = __float2bfloat16_rn(x - __bfloat162float(h));
}

__device__ __forceinline__ void mma_bf16(float c[4], const unsigned a[4], const unsigned b[2]) {
    asm volatile(
        "mma.sync.aligned.m16n8k16.row.col.f32.bf16.bf16.f32 "
        "{%0,%1,%2,%3}, {%4,%5,%6,%7}, {%8,%9}, {%0,%1,%2,%3};"
        : "+f"(c[0]), "+f"(c[1]), "+f"(c[2]), "+f"(c[3])
        : "r"(a[0]), "r"(a[1]), "r"(a[2]), "r"(a[3]), "r"(b[0]), "r"(b[1]));
}

__device__ __forceinline__ void cp16s(unsigned saddr, const void* gsrc) {
    asm volatile("cp.async.cg.shared.global [%0], [%1], 16;\n" :: "r"(saddr), "l"(gsrc));
}

__device__ __forceinline__ void ldsm4(unsigned &r0, unsigned &r1, unsigned &r2,
                                      unsigned &r3, unsigned addr) {
    asm volatile("ldmatrix.sync.aligned.m8n8.x4.shared.b16 {%0,%1,%2,%3}, [%4];"
                 : "=r"(r0), "=r"(r1), "=r"(r2), "=r"(r3) : "r"(addr));
}

__device__ __forceinline__ float blockSum(float v, float* sh) {
    __syncthreads();
    int lane = threadIdx.x & 31, w = threadIdx.x >> 5;
#pragma unroll
    for (int o = 16; o; o >>= 1) v += __shfl_xor_sync(0xffffffffu, v, o);
    if (lane == 0) sh[w] = v;
    __syncthreads();
    if (threadIdx.x == 0) {
        float s = 0.f; int nw = blockDim.x >> 5;
        for (int i = 0; i < nw; i++) s += sh[i];
        sh[32] = s;
    }
    __syncthreads();
    return sh[32];
}

__device__ __forceinline__ float blockMax(float v, float* sh) {
    __syncthreads();
    int lane = threadIdx.x & 31, w = threadIdx.x >> 5;
#pragma unroll
    for (int o = 16; o; o >>= 1) v = fmaxf(v, __shfl_xor_sync(0xffffffffu, v, o));
    if (lane == 0) sh[w] = v;
    __syncthreads();
    if (threadIdx.x == 0) {
        float s = -3.4e38f; int nw = blockDim.x >> 5;
        for (int i = 0; i < nw; i++) s = fmaxf(s, sh[i]);
        sh[32] = s;
    }
    __syncthreads();
    return sh[32];
}

// ---------------- split-bf16 tensor-core GEMM -----------------------------------
// A: [M,K] hi/lo bf16 k-contiguous; B: [N,K] hi/lo bf16. C = A·B^T.
// BM: M-tile (128 or 64). 64 = higher grid parallelism for small-M GEMMs.
// ONETERM=false: 3-term compensation (hh + hl + lh) => ~fp32 accuracy.
// ONETERM=true : hh only (approximate, for ranking).
// AIDX: A-rows gathered via rowlist; dynamic M via *cntp with block early-exit.
// XROW: blockIdx.x indexes rows (fast-varying). Grid must be (M/BM, N/128).
// MODE 0: +bias   MODE 1: relu(+bias)   MODE 2: +bias+res
// MODE 3: colv[n]-2*AB -> bf16 key into Chi (ranking only)
// MODE 4: AB+res+rowv[m]*bias[n]+colv[n]
// RESSPLIT: res from bf16 hi/lo pair.  DONORM: atomicAdd row sumsq->normout.

template<int BM, int MODE, bool WF32, bool WSPLIT, bool RESSPLIT, bool DONORM, bool ONETERM,
         bool AIDX, bool XROW>
__global__ void __launch_bounds__(256, 2) gemm_bf16s_k(
    int M, int N, int K,
    const bf16* __restrict__ Ahg, const bf16* __restrict__ Alg,
    const bf16* __restrict__ Bhg, const bf16* __restrict__ Blg,
    const float* __restrict__ bias, const float* __restrict__ res,
    const bf16* __restrict__ resbh, const bf16* __restrict__ resbl,
    const float* __restrict__ rowv, const float* __restrict__ colv,
    float* __restrict__ C, bf16* __restrict__ Chi, bf16* __restrict__ Clo,
    float* __restrict__ normout,
    const int* __restrict__ rowlist, const int* __restrict__ cntp)
{
    constexpr int MI    = BM / 32;            // m-frags per warp (warp tile = BM/2)
    constexpr int ATB   = BM * 64;            // A tile bytes (per hi/lo)
    constexpr int OFF_AL = ATB;
    constexpr int OFF_BH = 2 * ATB;
    constexpr int OFF_BL = 2 * ATB + 8192;
    constexpr int STAGE  = 2 * ATB + 16384;

    extern __shared__ __align__(1024) char smem[];
    const unsigned sbase = (unsigned)__cvta_generic_to_shared(smem);

    const int tid  = threadIdx.x;
    const int lane = tid & 31;
    const int wid  = tid >> 5;
    const int wm   = (wid & 1) * (BM / 2);
    const int wn   = (wid >> 1) * 32;
    const int grp  = lane >> 2;
    const int thr  = lane & 3;

    const long rowBase = XROW ? (long)blockIdx.x * BM : (long)blockIdx.y * BM;
    const long colBase = XROW ? (long)blockIdx.y * 128 : (long)blockIdx.x * 128;

    if (AIDX) {
        if (rowBase >= (long)*cntp) return;    // dynamic M early-exit
    }

    // A-row source indices for fill (BM/64 chunks of 64 rows)
    long arows[BM / 64];
#pragma unroll
    for (int i = 0; i < BM / 64; i++) {
        const long r = rowBase + (tid >> 2) + i * 64;
        arows[i] = AIDX ? (long)rowlist[r] : r;
    }

    float acc[MI][4][4];
#pragma unroll
    for (int mi = 0; mi < MI; mi++)
#pragma unroll
        for (int ni = 0; ni < 4; ni++)
#pragma unroll
            for (int j = 0; j < 4; j++) acc[mi][ni][j] = 0.f;

    const int T = K >> 5;    // 32-elem chunks

    auto fill = [&](int s, int t) {
        const int k0 = t << 5;
        const unsigned sb = sbase + (unsigned)s * STAGE;
#pragma unroll
        for (int i = 0; i < BM / 64; i++) {       // A tiles
            int q = tid + i * 256;
            int r = q >> 2, c = q & 3;
            int off = r * 64 + c * 16;
            int sw  = off ^ ((off >> 3) & 0x30);
            const long ao = arows[i] * (long)K + k0 + c * 8;
            cp16s(sb + sw, Ahg + ao);
            if (!ONETERM) cp16s(sb + OFF_AL + sw, Alg + ao);
        }
#pragma unroll
        for (int i = 0; i < 2; i++) {             // B tiles (always 128 rows)
            int q = tid + i * 256;
            int r = q >> 2, c = q & 3;
            int off = r * 64 + c * 16;
            int sw  = off ^ ((off >> 3) & 0x30);
            const long bo = (colBase + r) * (long)K + k0 + c * 8;
            cp16s(sb + OFF_BH + sw, Bhg + bo);
            if (!ONETERM) cp16s(sb + OFF_BL + sw, Blg + bo);
        }
        asm volatile("cp.async.commit_group;" ::: "memory");
    };

    const int aRow16 = lane & 15;
    const int aKx    = (lane & 16) ? 16 : 0;
    const int bRowO  = (lane & 7) + ((lane & 16) ? 8 : 0);
    const int bKx    = (lane & 8) ? 16 : 0;

    fill(0, 0);
    if (T > 1) fill(1, 1);

    for (int t = 0; t < T; t++) {
        if (t < T - 1) asm volatile("cp.async.wait_group 1;" ::: "memory");
        else           asm volatile("cp.async.wait_group 0;" ::: "memory");
        __syncthreads();
        if (t + 2 < T) fill((t + 2) % 3, t + 2);

        const unsigned ab  = sbase + (unsigned)(t % 3) * STAGE;
        const unsigned alb = ab + OFF_AL, bb = ab + OFF_BH, blb = ab + OFF_BL;

#pragma unroll
        for (int s16 = 0; s16 < 64; s16 += 32) {
            unsigned ah[MI][4], al[MI][4];
#pragma unroll
            for (int mi = 0; mi < MI; mi++) {
                int rowb = (wm + mi * 16 + aRow16) * 64;
                unsigned msk = (unsigned)((rowb >> 3) & 0x30);
                ldsm4(ah[mi][0], ah[mi][1], ah[mi][2], ah[mi][3],
                      (ab + rowb + s16 + aKx) ^ msk);
                if (!ONETERM)
                    ldsm4(al[mi][0], al[mi][1], al[mi][2], al[mi][3],
                          (alb + rowb + s16 + aKx) ^ msk);
            }
#pragma unroll
            for (int p = 0; p < 2; p++) {
                int rowb = (wn + p * 16 + bRowO) * 64;
                unsigned msk = (unsigned)((rowb >> 3) & 0x30);
                unsigned bh[4], bl[4];
                ldsm4(bh[0], bh[1], bh[2], bh[3], (bb + rowb + s16 + bKx) ^ msk);
                if (!ONETERM)
                    ldsm4(bl[0], bl[1], bl[2], bl[3], (blb + rowb + s16 + bKx) ^ msk);
                // term-major: independent MMAs between same-acc reuses
#pragma unroll
                for (int mi = 0; mi < MI; mi++) {
                    mma_bf16(acc[mi][2 * p],     ah[mi], &bh[0]);
                    mma_bf16(acc[mi][2 * p + 1], ah[mi], &bh[2]);
                }
                if (!ONETERM) {
#pragma unroll
                    for (int mi = 0; mi < MI; mi++) {
                        mma_bf16(acc[mi][2 * p],     ah[mi], &bl[0]);
                        mma_bf16(acc[mi][2 * p + 1], ah[mi], &bl[2]);
                    }
#pragma unroll
                    for (int mi = 0; mi < MI; mi++) {
                        mma_bf16(acc[mi][2 * p],     al[mi], &bh[0]);
                        mma_bf16(acc[mi][2 * p + 1], al[mi], &bh[2]);
                    }
                }
            }
        }
    }

    // ---- epilogue ----------------------------------------------------------
#pragma unroll
    for (int mi = 0; mi < MI; mi++) {
#pragma unroll
        for (int half = 0; half < 2; half++) {
            const long rr = rowBase + wm + mi * 16 + grp + half * 8;
            const float rv = (MODE == 4) ? rowv[rr] : 0.f;
            float ss = 0.f;
#pragma unroll
            for (int ni = 0; ni < 4; ni++) {
                const long c = colBase + wn + ni * 8 + thr * 2;
                float o0 = acc[mi][ni][half * 2 + 0];
                float o1 = acc[mi][ni][half * 2 + 1];
                if (MODE == 0 || MODE == 1 || MODE == 2) {
                    if (bias) { o0 += bias[c]; o1 += bias[c + 1]; }
                }
                if (MODE == 2) {
                    if (RESSPLIT) {
                        ushort2 rh = *(const ushort2*)&resbh[rr * N + c];
                        ushort2 rl = *(const ushort2*)&resbl[rr * N + c];
                        o0 += __bfloat162float(__ushort_as_bfloat16(rh.x))
                            + __bfloat162float(__ushort_as_bfloat16(rl.x));
                        o1 += __bfloat162float(__ushort_as_bfloat16(rh.y))
                            + __bfloat162float(__ushort_as_bfloat16(rl.y));
                    } else {
                        o0 += res[rr * N + c]; o1 += res[rr * N + c + 1];
                    }
                }
                if (MODE == 1) { o0 = fmaxf(o0, 0.f); o1 = fmaxf(o1, 0.f); }
                if (MODE == 3) {
                    o0 = colv[c]     - 2.f * o0;
                    o1 = colv[c + 1] - 2.f * o1;
                    ushort2 kk;
                    kk.x = __bfloat16_as_ushort(__float2bfloat16_rn(o0));
                    kk.y = __bfloat16_as_ushort(__float2bfloat16_rn(o1));
                    *(ushort2*)&Chi[rr * N + c] = kk;
                }
                if (MODE == 4) {
                    o0 = o0 + res[rr * N + c]     + rv * bias[c]     + colv[c];
                    o1 = o1 + res[rr * N + c + 1] + rv * bias[c + 1] + colv[c + 1];
                }
                if (DONORM) ss += o0 * o0 + o1 * o1;
                if (WF32)
                    *(float2*)(C + rr * N + c) = make_float2(o0, o1);
                if (WSPLIT) {
                    bf16 h0, l0, h1, l1;
                    split1(o0, h0, l0);
                    split1(o1, h1, l1);
                    ushort2 hp, lp;
                    hp.x = __bfloat16_as_ushort(h0); hp.y = __bfloat16_as_ushort(h1);
                    lp.x = __bfloat16_as_ushort(l0); lp.y = __bfloat16_as_ushort(l1);
                    *(ushort2*)&Chi[rr * N + c] = hp;
                    *(ushort2*)&Clo[rr * N + c] = lp;
                }
            }
            if (DONORM) {
                ss += __shfl_xor_sync(0xffffffffu, ss, 1);
                ss += __shfl_xor_sync(0xffffffffu, ss, 2);
                if (thr == 0) atomicAdd(normout + rr, ss);
            }
        }
    }
}

// ---------------- init: norms, flags, compact list ------------------------------
__global__ void initsel_k(float* cnorm, int* flags, int* list, int* cnt)
{
    int i = blockIdx.x * 256 + threadIdx.x;
    if (i < NT)  cnorm[i] = 0.f;
    if (i < NC)  flags[i] = 0;
    if (i < NT)  list[i] = (i < BSZ) ? (NC + i) : 0;
    if (i == 0)  cnt[0] = BSZ;
}

// ---------------- mark used candidates, build compact list ----------------------
__global__ void mark_k(const int* __restrict__ idx, int* flags, int* remap,
                       int* list, int* cnt)
{
    int e = blockIdx.x * 256 + threadIdx.x;
    if (e >= BSZ * CC) return;
    int i = idx[e];
    if (atomicExch(&flags[i], 1) == 0) {
        int s = atomicAdd(cnt, 1);
        remap[i] = s;
        list[s] = i;
    }
}

// ---------------- split fp32 -> bf16 hi/lo (same layout) -----------------------
__global__ void split4_k(const float* __restrict__ in, bf16* __restrict__ oh,
                         bf16* __restrict__ ol, long n)
{
    long i = ((long)blockIdx.x * blockDim.x + threadIdx.x) * 4;
    if (i >= n) return;
    float4 v = *(const float4*)(in + i);
    bf16 h0,l0,h1,l1,h2,l2,h3,l3;
    split1(v.x,h0,l0); split1(v.y,h1,l1); split1(v.z,h2,l2); split1(v.w,h3,l3);
    ushort4 hp, lp;
    hp.x=__bfloat16_as_ushort(h0); hp.y=__bfloat16_as_ushort(h1);
    hp.z=__bfloat16_as_ushort(h2); hp.w=__bfloat16_as_ushort(h3);
    lp.x=__bfloat16_as_ushort(l0); lp.y=__bfloat16_as_ushort(l1);
    lp.z=__bfloat16_as_ushort(l2); lp.w=__bfloat16_as_ushort(l3);
    *(ushort4*)&oh[i] = hp;
    *(ushort4*)&ol[i] = lp;
}

// ---------------- weight split + transpose: [K,N] fp32 -> [N,K] bf16 hi/lo -----
__global__ void wsplitT_k(const float* __restrict__ in, int K, int N,
                          bf16* __restrict__ oh, bf16* __restrict__ ol)
{
    __shared__ float tile[32][33];
    int n0 = blockIdx.x * 32, k0 = blockIdx.y * 32;
    int tx = threadIdx.x, ty = threadIdx.y;   // 32 x 8
#pragma unroll
    for (int j = 0; j < 4; j++)
        tile[ty + j * 8][tx] = in[(long)(k0 + ty + j * 8) * N + n0 + tx];
    __syncthreads();
#pragma unroll
    for (int j = 0; j < 4; j++) {
        float v = tile[tx][ty + j * 8];
        bf16 h, l; split1(v, h, l);
        long o = (long)(n0 + ty + j * 8) * K + k0 + tx;
        oh[o] = h; ol[o] = l;
    }
}

// ------- warp-per-row layernorm (width 512) -> split bf16, no block syncs -------
__global__ void ln512w_split_k(const float* __restrict__ in, const float* __restrict__ g,
                               const float* __restrict__ b,
                               bf16* __restrict__ oh, bf16* __restrict__ ol)
{
    const int warp = threadIdx.x >> 5, lane = threadIdx.x & 31;
    const long row = (long)blockIdx.x * 8 + warp;
    const float* x = in + row * DD;

    float4 v[4];
    float s = 0.f;
#pragma unroll
    for (int j = 0; j < 4; j++) {
        v[j] = *(const float4*)(x + (lane + 32 * j) * 4);
        s += v[j].x + v[j].y + v[j].z + v[j].w;
    }
#pragma unroll
    for (int o = 16; o; o >>= 1) s += __shfl_xor_sync(0xffffffffu, s, o);
    const float m = s * (1.f / DD);

    float var = 0.f;
#pragma unroll
    for (int j = 0; j < 4; j++) {
        v[j].x -= m; v[j].y -= m; v[j].z -= m; v[j].w -= m;
        var += v[j].x * v[j].x + v[j].y * v[j].y + v[j].z * v[j].z + v[j].w * v[j].w;
    }
#pragma unroll
    for (int o = 16; o; o >>= 1) var += __shfl_xor_sync(0xffffffffu, var, o);
    const float inv = rsqrtf(var * (1.f / DD) + 1e-5f);

#pragma unroll
    for (int j = 0; j < 4; j++) {
        const int c = (lane + 32 * j) * 4;
        float4 gg = *(const float4*)(g + c);
        float4 bb = *(const float4*)(b + c);
        float o0 = v[j].x * inv * gg.x + bb.x;
        float o1 = v[j].y * inv * gg.y + bb.y;
        float o2 = v[j].z * inv * gg.z + bb.z;
        float o3 = v[j].w * inv * gg.w + bb.w;
        bf16 h0,l0,h1,l1,h2,l2,h3,l3;
        split1(o0,h0,l0); split1(o1,h1,l1); split1(o2,h2,l2); split1(o3,h3,l3);
        ushort4 hp, lp;
        hp.x=__bfloat16_as_ushort(h0); hp.y=__bfloat16_as_ushort(h1);
        hp.z=__bfloat16_as_ushort(h2); hp.w=__bfloat16_as_ushort(h3);
        lp.x=__bfloat16_as_ushort(l0); lp.y=__bfloat16_as_ushort(l1);
        lp.z=__bfloat16_as_ushort(l2); lp.w=__bfloat16_as_ushort(l3);
        *(ushort4*)&oh[row * DD + c] = hp;
        *(ushort4*)&ol[row * DD + c] = lp;
    }
}

// -------- top-96 on bf16 keys: 2-level 8-bit compacting radix select -----------
__device__ __forceinline__ unsigned fkey16(unsigned u) {
    return (u & 0x8000u) ? (~u & 0xFFFFu) : (u | 0x8000u);
}

__global__ void topk96b_k(const unsigned short* __restrict__ keys,
                          unsigned* __restrict__ bufA, int* __restrict__ idxo)
{
    const int b = blockIdx.x, tid = threadIdx.x;   // 256 threads
    const unsigned short* row = keys + (long)b * NC;
    unsigned* A = bufA + (long)b * NC;
    int* out = idxo + b * CC;

    __shared__ int hist[256];
    __shared__ int s_fill, s_cnt, s_bucket, s_need;

    hist[tid] = 0;
    if (tid == 0) { s_fill = 0; s_cnt = 0; }
    __syncthreads();

    const uint4* row4 = (const uint4*)row;
    for (int i = tid; i < NC / 8; i += 256) {
        uint4 v = row4[i];
        unsigned w[4] = {v.x, v.y, v.z, v.w};
#pragma unroll
        for (int j = 0; j < 4; j++) {
            atomicAdd(&hist[fkey16(w[j] & 0xFFFFu) >> 8], 1);
            atomicAdd(&hist[fkey16(w[j] >> 16) >> 8], 1);
        }
    }
    __syncthreads();
    if (tid == 0) {
        int cum = 0;
        for (int bin = 0; bin < 256; bin++) {
            int h = hist[bin];
            if (cum + h >= CC) { s_bucket = bin; s_need = CC - cum; break; }
            cum += h;
        }
    }
    __syncthreads();
    const unsigned b0 = (unsigned)s_bucket;
    for (int i = tid; i < NC; i += 256) {
        unsigned k = fkey16((unsigned)row[i]);
        unsigned hb = k >> 8;
        if (hb < b0)       out[atomicAdd(&s_fill, 1)] = i;
        else if (hb == b0) A[atomicAdd(&s_cnt, 1)] = (k << 16) | (unsigned)i;
    }
    __syncthreads();
    const int m = s_cnt;

    hist[tid] = 0;
    __syncthreads();
    for (int i = tid; i < m; i += 256)
        atomicAdd(&hist[(A[i] >> 16) & 0xFFu], 1);
    __syncthreads();
    if (tid == 0) {
        int cum = 0, need = s_need;
        for (int bin = 0; bin < 256; bin++) {
            int h = hist[bin];
            if (cum + h >= need) { s_bucket = bin; break; }
            cum += h;
        }
    }
    __syncthreads();
    const unsigned b1 = (unsigned)s_bucket;
    for (int i = tid; i < m; i += 256) {
        unsigned e = A[i];
        if (((e >> 16) & 0xFFu) < b1)
            out[atomicAdd(&s_fill, 1)] = (int)(e & 0xFFFFu);
    }
    __syncthreads();
    for (int i = tid; i < m; i += 256) {
        unsigned e = A[i];
        if (((e >> 16) & 0xFFu) == b1) {
            int p = atomicAdd(&s_fill, 1);
            if (p < CC) out[p] = (int)(e & 0xFFFFu);
        }
    }
}

// ------- exact rescore of the 96 selected + softmax + ybar ----------------------
__global__ void rescore96_k(const bf16* __restrict__ kxh, const bf16* __restrict__ kxl,
                            const bf16* __restrict__ kh,  const bf16* __restrict__ kl,
                            const float* __restrict__ cnorm, const int* __restrict__ idx,
                            const float* __restrict__ cy,
                            float* __restrict__ probs, float* __restrict__ ybar)
{
    const int b = blockIdx.x, tid = threadIdx.x;   // 256 threads, 8 warps
    const int warp = tid >> 5, lane = tid & 31;
    __shared__ float q[DD];
    __shared__ float sims[CC];
    __shared__ int   sidx[CC];
    __shared__ float sh[33];

    for (int i = tid; i < DD; i += 256)
        q[i] = __bfloat162float(kxh[(long)b * DD + i]) +
               __bfloat162float(kxl[(long)b * DD + i]);
    if (tid < CC) sidx[tid] = idx[b * CC + tid];
    __syncthreads();

    for (int c = warp; c < CC; c += 8) {
        const long base = (long)sidx[c] * DD + lane * 16;
        uint4 h0 = *(const uint4*)(kh + base);
        uint4 h1 = *(const uint4*)(kh + base + 8);
        uint4 l0 = *(const uint4*)(kl + base);
        uint4 l1 = *(const uint4*)(kl + base + 8);
        const unsigned hw[8] = {h0.x, h0.y, h0.z, h0.w, h1.x, h1.y, h1.z, h1.w};
        const unsigned lw[8] = {l0.x, l0.y, l0.z, l0.w, l1.x, l1.y, l1.z, l1.w};
        float dot = 0.f;
#pragma unroll
        for (int j = 0; j < 8; j++) {
            float c0 = __bfloat162float(__ushort_as_bfloat16((unsigned short)(hw[j] & 0xFFFF)))
                     + __bfloat162float(__ushort_as_bfloat16((unsigned short)(lw[j] & 0xFFFF)));
            float c1 = __bfloat162float(__ushort_as_bfloat16((unsigned short)(hw[j] >> 16)))
                     + __bfloat162float(__ushort_as_bfloat16((unsigned short)(lw[j] >> 16)));
            dot += q[lane * 16 + 2 * j] * c0 + q[lane * 16 + 2 * j + 1] * c1;
        }
#pragma unroll
        for (int o = 16; o; o >>= 1) dot += __shfl_xor_sync(0xffffffffu, dot, o);
        if (lane == 0) sims[c] = 2.f * dot - cnorm[sidx[c]];
    }
    __syncthreads();

    float sim = (tid < CC) ? sims[tid] : -3.4e38f;
    float mx = blockMax(sim, sh);
    float e = (tid < CC) ? expf(sim - mx) : 0.f;
    float s = blockSum(e, sh);
    float p = e / s;
    if (tid < CC) probs[b * CC + tid] = p;
    float yv = (tid < CC) ? p * cy[sidx[tid]] : 0.f;
    float yb = blockSum(yv, sh);
    if (tid == 0) ybar[b] = yb;
}

// ---- s[b,:] = sum_c probs * relu(kproj + T_b1 - cproj[remap[idx]]) -------------
__global__ void ctxsum_split_k(const float* __restrict__ cproj,
                               const float* __restrict__ tb1,
                               const int* __restrict__ idx, const int* __restrict__ remap,
                               const float* __restrict__ probs,
                               bf16* __restrict__ oh, bf16* __restrict__ ol)
{
    const int b = blockIdx.x, j = threadIdx.x;   // 1024 threads
    __shared__ int   si[CC];
    __shared__ float sp[CC];
    if (j < CC) { si[j] = remap[idx[b * CC + j]]; sp[j] = probs[b * CC + j]; }
    __syncthreads();
    float kp = cproj[(long)b * DBD + j] + tb1[j];    // queries occupy slots 0..BSZ
    float acc = 0.f;
#pragma unroll 4
    for (int c = 0; c < CC; c++) {
        float v = kp - cproj[(long)si[c] * DBD + j];
        acc += sp[c] * fmaxf(v, 0.f);
    }
    bf16 h, l; split1(acc, h, l);
    oh[(long)b * DBD + j] = h;
    ol[(long)b * DBD + j] = l;
}

// ---------------- head: relu(ln(x)) @ h_W + h_b ---------------------------------
__global__ void head512_k(const float* __restrict__ in, const float* __restrict__ g,
                          const float* __restrict__ bb, const float* __restrict__ hW,
                          const float* __restrict__ hb, float* __restrict__ out)
{
    __shared__ float sh[33];
    const long row = blockIdx.x;
    const float* x = in + row * DD;
    int t = threadIdx.x;
    float a = x[t], c = x[t + 256];
    float m = blockSum(a + c, sh) * (1.f / DD);
    float d0 = a - m, d1 = c - m;
    float v = blockSum(d0 * d0 + d1 * d1, sh) * (1.f / DD);
    float inv = rsqrtf(v + 1e-5f);
    float s0 = fmaxf(d0 * inv * g[t] + bb[t], 0.f) * hW[t];
    float s1 = fmaxf(d1 * inv * g[t + 256] + bb[t + 256], 0.f) * hW[t + 256];
    float tot = blockSum(s0 + s1, sh);
    if (t == 0) out[row] = tot + hb[0];
}

// ---------------- host side -----------------------------------------------------
template<typename T>
static T* devptr(const void* sym) {
    void* p = nullptr;
    cudaGetSymbolAddress(&p, sym);
    return (T*)p;
}

template<int BM, int MODE, bool WF32, bool WSPLIT, bool RESSPLIT, bool DONORM, bool ONETERM,
         bool AIDX = false, bool XROW = false>
static void launch_gemm(int M, int N, int K,
                        const bf16* Ah, const bf16* Al, const bf16* Bh, const bf16* Bl,
                        const float* bias, const float* res,
                        const bf16* resbh, const bf16* resbl,
                        const float* rowv, const float* colv,
                        float* C, bf16* Chi, bf16* Clo, float* normout,
                        const int* rowlist = nullptr, const int* cntp = nullptr) {
    constexpr int SMEMB = 3 * (2 * BM * 64 + 16384);
    cudaFuncSetAttribute(gemm_bf16s_k<BM, MODE, WF32, WSPLIT, RESSPLIT, DONORM, ONETERM, AIDX, XROW>,
                         cudaFuncAttributeMaxDynamicSharedMemorySize, SMEMB);
    dim3 grid = XROW ? dim3(M / BM, N / 128) : dim3(N / 128, M / BM);
    gemm_bf16s_k<BM, MODE, WF32, WSPLIT, RESSPLIT, DONORM, ONETERM, AIDX, XROW><<<grid, 256, SMEMB>>>(
        M, N, K, Ah, Al, Bh, Bl, bias, res, resbh, resbl, rowv, colv,
        C, Chi, Clo, normout, rowlist, cntp);
}

extern "C" void kernel_launch(void* const* d_in, const int* in_sizes, int n_in,
                              void* d_out, int out_size)
{
    const float* x_num  = (const float*)d_in[0];
    const float* cand   = (const float*)d_in[1];
    const float* cy     = (const float*)d_in[2];
    const float* lin_W  = (const float*)d_in[3];
    const float* lin_b  = (const float*)d_in[4];
    const float* e_W1   = (const float*)d_in[5];
    const float* e_b1   = (const float*)d_in[6];
    const float* e_W2   = (const float*)d_in[7];
    const float* e_b2   = (const float*)d_in[8];
    const float* mix_g  = (const float*)d_in[9];
    const float* mix_b  = (const float*)d_in[10];
    const float* K_W    = (const float*)d_in[11];
    const float* K_b    = (const float*)d_in[12];
    const float* lab_W  = (const float*)d_in[13];
    const float* lab_b  = (const float*)d_in[14];
    const float* T_W1   = (const float*)d_in[15];
    const float* T_b1   = (const float*)d_in[16];
    const float* T_W2   = (const float*)d_in[17];
    const float* p_ln_g = (const float*)d_in[18];
    const float* p_ln_b = (const float*)d_in[19];
    const float* p_W1   = (const float*)d_in[20];
    const float* p_b1   = (const float*)d_in[21];
    const float* p_W2   = (const float*)d_in[22];
    const float* p_b2   = (const float*)d_in[23];
    const float* h_ln_g = (const float*)d_in[24];
    const float* h_ln_b = (const float*)d_in[25];
    const float* h_W    = (const float*)d_in[26];
    const float* h_b    = (const float*)d_in[27];
    float* out = (float*)d_out;

    float* p_h     = devptr<float>(g_h);
    float* p_cproj = devptr<float>(g_cproj);
    float* p_cnorm = devptr<float>(g_cnorm);
    unsigned short* p_keys = devptr<unsigned short>(g_keys);
    unsigned* p_bufA = devptr<unsigned>(g_bufA);
    int*   p_idx   = devptr<int>(g_idx);
    float* p_probs = devptr<float>(g_probs);
    float* p_ybar  = devptr<float>(g_ybar);
    float* p_x2    = devptr<float>(g_x2);
    float* p_x3    = devptr<float>(g_x3);
    int* p_flags = devptr<int>(g_flags);
    int* p_remap = devptr<int>(g_remap);
    int* p_list  = devptr<int>(g_list);
    int* p_cnt   = devptr<int>(g_cnt);

    bf16 *candh = devptr<bf16>(g_candh), *candl = devptr<bf16>(g_candl);
    bf16 *hh = devptr<bf16>(g_hh),   *hl = devptr<bf16>(g_hl);
    bf16 *th = devptr<bf16>(g_th),   *tl = devptr<bf16>(g_tl);
    bf16 *hnh = devptr<bf16>(g_hnh), *hnl = devptr<bf16>(g_hnl);
    bf16 *kh = devptr<bf16>(g_kh),   *kl = devptr<bf16>(g_kl);
    bf16 *xnh = devptr<bf16>(g_xnh), *xnl = devptr<bf16>(g_xnl);
    bf16 *sh_ = devptr<bf16>(g_sh),  *sl_ = devptr<bf16>(g_sl);

    bf16 *wlinh = devptr<bf16>(g_wlinh), *wlinl = devptr<bf16>(g_wlinl);
    bf16 *we1h = devptr<bf16>(g_we1h),   *we1l = devptr<bf16>(g_we1l);
    bf16 *we2h = devptr<bf16>(g_we2h),   *we2l = devptr<bf16>(g_we2l);
    bf16 *wKh = devptr<bf16>(g_wKh),     *wKl = devptr<bf16>(g_wKl);
    bf16 *wT1h = devptr<bf16>(g_wT1h),   *wT1l = devptr<bf16>(g_wT1l);
    bf16 *wT2h = devptr<bf16>(g_wT2h),   *wT2l = devptr<bf16>(g_wT2l);
    bf16 *wp1h = devptr<bf16>(g_wp1h),   *wp1l = devptr<bf16>(g_wp1l);
    bf16 *wp2h = devptr<bf16>(g_wp2h),   *wp2l = devptr<bf16>(g_wp2l);

    // merged-row views (query rows appended after candidate rows)
    bf16 *kqh = kh + (long)NC * DD, *kql = kl + (long)NC * DD;   // query k
    float* p_hx = p_h + (long)NC * DD;                           // query encoder out

    // ---- one-time prep ------------------------------------------------------
    split4_k<<<(NC * FD / 4 + 255) / 256, 256>>>(cand, candh, candl, (long)NC * FD);
    split4_k<<<(BSZ * FD / 4 + 255) / 256, 256>>>(x_num, candh + (long)NC * FD,
                                                  candl + (long)NC * FD, (long)BSZ * FD);
    initsel_k<<<(NT + 255) / 256, 256>>>(p_cnorm, p_flags, p_list, p_cnt);
    {
        dim3 blk(32, 8);
        wsplitT_k<<<dim3(DD / 32, FD / 32), blk>>>(lin_W, FD, DD, wlinh, wlinl);
        wsplitT_k<<<dim3(DBD / 32, DD / 32), blk>>>(e_W1, DD, DBD, we1h, we1l);
        wsplitT_k<<<dim3(DD / 32, DBD / 32), blk>>>(e_W2, DBD, DD, we2h, we2l);
        wsplitT_k<<<dim3(DD / 32, DD / 32), blk>>>(K_W, DD, DD, wKh, wKl);
        wsplitT_k<<<dim3(DBD / 32, DD / 32), blk>>>(T_W1, DD, DBD, wT1h, wT1l);
        wsplitT_k<<<dim3(DD / 32, DBD / 32), blk>>>(T_W2, DBD, DD, wT2h, wT2l);
        wsplitT_k<<<dim3(DBD / 32, DD / 32), blk>>>(p_W1, DD, DBD, wp1h, wp1l);
        wsplitT_k<<<dim3(DD / 32, DBD / 32), blk>>>(p_W2, DBD, DD, wp2h, wp2l);
    }

    // ---- merged encoder (candidates + queries in one chain) ------------------
    launch_gemm<128, 0, false, true, false, false, false>(NT, DD, FD, candh, candl, wlinh, wlinl,
        lin_b, nullptr, nullptr, nullptr, nullptr, nullptr, nullptr, hh, hl, nullptr);
    launch_gemm<128, 1, false, true, false, false, false>(NT, DBD, DD, hh, hl, we1h, we1l,
        e_b1, nullptr, nullptr, nullptr, nullptr, nullptr, nullptr, th, tl, nullptr);
    launch_gemm<128, 2, true, false, true, false, false>(NT, DD, DBD, th, tl, we2h, we2l,
        e_b2, nullptr, hh, hl, nullptr, nullptr, p_h, nullptr, nullptr, nullptr);
    ln512w_split_k<<<NT / 8, 256>>>(p_h, mix_g, mix_b, hnh, hnl);
    launch_gemm<128, 0, false, true, false, true, false>(NT, DD, DD, hnh, hnl, wKh, wKl,
        K_b, nullptr, nullptr, nullptr, nullptr, nullptr, nullptr, kh, kl, p_cnorm);

    // ---- kNN: approx bf16 ranking keys (XROW: B tiles L2-shared) --------------
    launch_gemm<128, 3, false, false, false, false, true, false, true>(BSZ, NC, DD, kqh, kql, kh, kl,
        nullptr, nullptr, nullptr, nullptr, nullptr, p_cnorm, nullptr,
        (bf16*)p_keys, nullptr, nullptr);
    topk96b_k<<<BSZ, 256>>>(p_keys, p_bufA, p_idx);
    rescore96_k<<<BSZ, 256>>>(kqh, kql, kh, kl, p_cnorm, p_idx, cy, p_probs, p_ybar);

    // ---- T1 projection over [queries | used candidates] only -----------------
    mark_k<<<(BSZ * CC + 255) / 256, 256>>>(p_idx, p_flags, p_remap, p_list, p_cnt);
    launch_gemm<128, 0, true, false, false, false, false, true>(NT, DBD, DD, kh, kl, wT1h, wT1l,
        nullptr, nullptr, nullptr, nullptr, nullptr, nullptr, p_cproj, nullptr, nullptr, nullptr,
        p_list, p_cnt);

    // ---- context aggregation (BM=64 tiles: small-M GEMMs need grid parallelism)
    ctxsum_split_k<<<BSZ, 1024>>>(p_cproj, T_b1, p_idx, p_remap, p_probs, sh_, sl_);
    launch_gemm<64, 4, true, false, false, false, false>(BSZ, DD, DBD, sh_, sl_, wT2h, wT2l,
        lab_W, p_hx, nullptr, nullptr, p_ybar, lab_b, p_x2, nullptr, nullptr, nullptr);

    // ---- predictor block + head -------------------------------------------
    ln512w_split_k<<<BSZ / 8, 256>>>(p_x2, p_ln_g, p_ln_b, xnh, xnl);
    launch_gemm<64, 1, false, true, false, false, false>(BSZ, DBD, DD, xnh, xnl, wp1h, wp1l,
        p_b1, nullptr, nullptr, nullptr, nullptr, nullptr, nullptr, th, tl, nullptr);
    launch_gemm<64, 2, true, false, false, false, false>(BSZ, DD, DBD, th, tl, wp2h, wp2l,
        p_b2, p_x2, nullptr, nullptr, nullptr, nullptr, p_x3, nullptr, nullptr, nullptr);
    head512_k<<<BSZ, 256>>>(p_x3, h_ln_g, h_ln_b, h_W, h_b, out);

    (void)in_sizes; (void)n_in; (void)out_size;
}